// round 10
// baseline (speedup 1.0000x reference)
#include <cuda_runtime.h>
#include <cstdint>

#define B_ 8
#define N_ 16384
#define M_ 1024
#define C_ 64
#define NS_ 32
#define COUT_ 67
#define R2_ 0.04f

#define FEAT_BLOCKS (B_ * C_)   // 512
#define XYZ_BLOCKS  (B_ * 3)    // 24
#define GD_SMEM ((N_ + M_) * 4) // 69632 bytes

// Scratch: ball-query indices (1 MB). No transposed-feature scratch anymore.
__device__ int g_idx[(size_t)B_ * M_ * NS_];

// ---------------------------------------------------------------------------
// Ball query helpers: 256-pt chunk = 768 float4; lane owns float4s
// [lane*6, lane*6+6) = points [chunk+8*lane, chunk+8*lane+8).
// ---------------------------------------------------------------------------
struct BqBuf { float4 f[6]; };

__device__ __forceinline__ void bq_load(const float4* __restrict__ base4,
                                        int tfo, BqBuf& b) {
#pragma unroll
    for (int k = 0; k < 6; k++) b.f[k] = base4[tfo + k];
}

__device__ __forceinline__ unsigned bq_mask(const BqBuf& b, float qx, float qy,
                                            float qz) {
    const float* s = (const float*)b.f;
    unsigned m = 0u;
#pragma unroll
    for (int j = 0; j < 8; j++) {
        const float dx = s[3 * j + 0] - qx;
        const float dy = s[3 * j + 1] - qy;
        const float dz = s[3 * j + 2] - qz;
        if (dx * dx + dy * dy + dz * dz < R2_) m |= 1u << j;
    }
    return m;
}

// Ordered placement (rare path). Order = chunk + 8*lane + j.
__device__ __forceinline__ void bq_place(unsigned mask, int chunk, int lane,
                                         int total, int* __restrict__ sidxw) {
    const int c = __popc(mask);
    int incl = c;
#pragma unroll
    for (int d = 1; d < 32; d <<= 1) {
        const int v = __shfl_up_sync(0xffffffffu, incl, d);
        if (lane >= d) incl += v;
    }
    int pos = total + (incl - c);
#pragma unroll
    for (int j = 0; j < 8; j++) {
        if ((mask >> j) & 1u) {
            if (pos < NS_) sidxw[pos] = chunk + lane * 8 + j;
            pos++;
        }
    }
}

// ---------------------------------------------------------------------------
// Kernel 1: ball query. 128-thread blocks, one warp per query (finer block
// retirement than 256-thr). Double-buffered 256-pt chunks; nibble + one
// redux fast path; placement only while total < 32.
// ---------------------------------------------------------------------------
__global__ void __launch_bounds__(128) ballquery_kernel(
    const float* __restrict__ xyz, const float* __restrict__ new_xyz) {
    __shared__ int sidx[4][NS_];

    const int tid  = threadIdx.x;
    const int w    = tid >> 5;
    const int lane = tid & 31;
    const int q    = blockIdx.x * 4 + w;
    const int b    = q >> 10;

    const float4* base4 = (const float4*)(xyz + (size_t)b * N_ * 3);
    const float*  qp    = new_xyz + (size_t)q * 3;
    const float qx = qp[0], qy = qp[1], qz = qp[2];
    const int tfo = lane * 6;

    int total = 0;
    BqBuf A, B;
    bq_load(base4, 0 * 192 + tfo, A);     // chunk 0   (n0/256*192 float4s)
    bq_load(base4, 1 * 192 + tfo, B);     // chunk 256

    for (int n0 = 0; n0 < N_; n0 += 512) {
        {
            const unsigned m = bq_mask(A, qx, qy, qz);
            if (n0 + 512 < N_) bq_load(base4, ((n0 + 512) >> 2) * 3 + tfo, A);
            const int cnt = __reduce_add_sync(0xffffffffu, __popc(m));
            if (cnt) {
                if (total < NS_) bq_place(m, n0, lane, total, sidx[w]);
                total += cnt;
                if (total >= NS_) break;
            }
        }
        {
            const unsigned m = bq_mask(B, qx, qy, qz);
            if (n0 + 768 < N_) bq_load(base4, ((n0 + 768) >> 2) * 3 + tfo, B);
            const int cnt = __reduce_add_sync(0xffffffffu, __popc(m));
            if (cnt) {
                if (total < NS_) bq_place(m, n0 + 256, lane, total, sidx[w]);
                total += cnt;
                if (total >= NS_) break;
            }
        }
    }

    __syncwarp();
    int v;
    if (total == 0) {
        v = N_ - 1;  // reference: all-invalid -> clamped gather
    } else {
        const int first = sidx[w][0];
        v = (lane < min(total, NS_)) ? sidx[w][lane] : first;
    }
    g_idx[(size_t)q * NS_ + lane] = v;
}

// ---------------------------------------------------------------------------
// Kernel 2: direct grouping, NO transpose. One block per (b, channel):
//   feature blocks (512): stage feats[b][c][0:16384] in smem (coalesced
//     float4), then out[b][3+c][m][s] = row[idx[b][m][s]] via int4 idx loads,
//     4 smem gathers, one STG.128. Output row is 128KB contiguous.
//   xyz blocks (24): same but row[n] = xyz[b][n][c], minus new_xyz[b][m][c].
// Traffic: 32MB feats read (once) + 70MB store + idx re-reads in L2.
// ---------------------------------------------------------------------------
__global__ void __launch_bounds__(256) group_direct_kernel(
    const float* __restrict__ xyz, const float* __restrict__ new_xyz,
    const float* __restrict__ feats, float* __restrict__ out) {
    extern __shared__ float row[];           // [N_] + [M_] for xyz path
    const int blk = blockIdx.x;
    const int t   = threadIdx.x;

    if (blk < FEAT_BLOCKS) {
        const int b = blk >> 6;
        const int c = blk & 63;

        const float4* src = (const float4*)(feats + ((size_t)b * C_ + c) * N_);
        float4* row4 = (float4*)row;
#pragma unroll
        for (int i = 0; i < 16; i++)
            row4[t + i * 256] = src[t + i * 256];
        __syncthreads();

        const int4* ib4 = (const int4*)(g_idx + (size_t)b * M_ * NS_);
        float4* ob4 = (float4*)(out + ((size_t)b * COUT_ + 3 + c) * (M_ * NS_));
#pragma unroll
        for (int e = 0; e < 32; e++) {
            const int i4 = t + e * 256;      // 8192 float4s = 1024*32 floats
            const int4 id = ib4[i4];
            float4 v;
            v.x = row[id.x]; v.y = row[id.y];
            v.z = row[id.z]; v.w = row[id.w];
            ob4[i4] = v;
        }
    } else {
        const int blk2 = blk - FEAT_BLOCKS;
        const int b = blk2 / 3;
        const int c = blk2 % 3;
        float* nq = row + N_;

        for (int i = t; i < N_; i += 256)
            row[i] = xyz[(size_t)b * N_ * 3 + (size_t)i * 3 + c];
        for (int i = t; i < M_; i += 256)
            nq[i] = new_xyz[(size_t)b * M_ * 3 + (size_t)i * 3 + c];
        __syncthreads();

        const int4* ib4 = (const int4*)(g_idx + (size_t)b * M_ * NS_);
        float4* ob4 = (float4*)(out + ((size_t)b * COUT_ + c) * (M_ * NS_));
#pragma unroll
        for (int e = 0; e < 32; e++) {
            const int i4 = t + e * 256;
            const int m  = i4 >> 3;          // 8 float4 segments per m
            const float qv = nq[m];
            const int4 id = ib4[i4];
            float4 v;
            v.x = row[id.x] - qv; v.y = row[id.y] - qv;
            v.z = row[id.z] - qv; v.w = row[id.w] - qv;
            ob4[i4] = v;
        }
    }
}

// ---------------------------------------------------------------------------
extern "C" void kernel_launch(void* const* d_in, const int* in_sizes, int n_in,
                              void* d_out, int out_size) {
    const float* xyz = nullptr;
    const float* new_xyz = nullptr;
    const float* feats = nullptr;
    for (int i = 0; i < n_in; i++) {
        if (in_sizes[i] == B_ * N_ * 3)      xyz     = (const float*)d_in[i];
        else if (in_sizes[i] == B_ * M_ * 3) new_xyz = (const float*)d_in[i];
        else if (in_sizes[i] == B_ * C_ * N_) feats  = (const float*)d_in[i];
    }
    float* out = (float*)d_out;

    cudaFuncSetAttribute(group_direct_kernel,
                         cudaFuncAttributeMaxDynamicSharedMemorySize, GD_SMEM);

    ballquery_kernel<<<(B_ * M_) / 4, 128>>>(xyz, new_xyz);
    group_direct_kernel<<<FEAT_BLOCKS + XYZ_BLOCKS, 256, GD_SMEM>>>(
        xyz, new_xyz, feats, out);
}

// round 11
// speedup vs baseline: 1.1462x; 1.1462x over previous
#include <cuda_runtime.h>
#include <cstdint>

#define B_ 8
#define N_ 16384
#define M_ 1024
#define C_ 64
#define NS_ 32
#define COUT_ 67
#define R2_ 0.04f

#define FEAT_BLOCKS (B_ * C_)   // 512
#define XYZ_BLOCKS  (B_ * 3)    // 24
#define GD_SMEM ((N_ + M_) * 4) // 69632 bytes

// Scratch: ball-query indices (1 MB).
__device__ int g_idx[(size_t)B_ * M_ * NS_];

// ---------------------------------------------------------------------------
// Ball query helpers: 256-pt chunk = 768 float4; lane owns float4s
// [lane*6, lane*6+6) = points [chunk+8*lane, chunk+8*lane+8).
// ---------------------------------------------------------------------------
struct BqBuf { float4 f[6]; };

__device__ __forceinline__ void bq_load(const float4* __restrict__ base4,
                                        int tfo, BqBuf& b) {
#pragma unroll
    for (int k = 0; k < 6; k++) b.f[k] = base4[tfo + k];
}

__device__ __forceinline__ unsigned bq_mask(const BqBuf& b, float qx, float qy,
                                            float qz) {
    const float* s = (const float*)b.f;
    unsigned m = 0u;
#pragma unroll
    for (int j = 0; j < 8; j++) {
        const float dx = s[3 * j + 0] - qx;
        const float dy = s[3 * j + 1] - qy;
        const float dz = s[3 * j + 2] - qz;
        if (dx * dx + dy * dy + dz * dz < R2_) m |= 1u << j;
    }
    return m;
}

// Hit-chunk path: ordered placement AND count. Order = chunk + 8*lane + j.
// Returns the chunk's total hit count (lane-31 inclusive prefix).
__device__ __forceinline__ int bq_place(unsigned mask, int chunk, int lane,
                                        int total, int* __restrict__ sidxw) {
    const int c = __popc(mask);
    int incl = c;
#pragma unroll
    for (int d = 1; d < 32; d <<= 1) {
        const int v = __shfl_up_sync(0xffffffffu, incl, d);
        if (lane >= d) incl += v;
    }
    int pos = total + (incl - c);
#pragma unroll
    for (int j = 0; j < 8; j++) {
        if ((mask >> j) & 1u) {
            if (pos < NS_) sidxw[pos] = chunk + lane * 8 + j;
            pos++;
        }
    }
    return __shfl_sync(0xffffffffu, incl, 31);
}

// ---------------------------------------------------------------------------
// Kernel 1: ball query. One warp per query. Double-buffered 256-pt chunks.
// Fast path per chunk: 24 FMA + ONE ballot (m != 0). Placement+count only on
// chunks containing hits (total is always < NS_ inside the loop).
// ---------------------------------------------------------------------------
__global__ void __launch_bounds__(128) ballquery_kernel(
    const float* __restrict__ xyz, const float* __restrict__ new_xyz) {
    __shared__ int sidx[4][NS_];

    const int tid  = threadIdx.x;
    const int w    = tid >> 5;
    const int lane = tid & 31;
    const int q    = blockIdx.x * 4 + w;
    const int b    = q >> 10;

    const float4* base4 = (const float4*)(xyz + (size_t)b * N_ * 3);
    const float*  qp    = new_xyz + (size_t)q * 3;
    const float qx = qp[0], qy = qp[1], qz = qp[2];
    const int tfo = lane * 6;

    int total = 0;
    BqBuf A, B;
    bq_load(base4, 0 * 192 + tfo, A);     // chunk 0
    bq_load(base4, 1 * 192 + tfo, B);     // chunk 256

    for (int n0 = 0; n0 < N_; n0 += 512) {
        {
            const unsigned m = bq_mask(A, qx, qy, qz);
            if (n0 + 512 < N_) bq_load(base4, ((n0 + 512) >> 2) * 3 + tfo, A);
            if (__ballot_sync(0xffffffffu, m != 0u)) {
                total += bq_place(m, n0, lane, total, sidx[w]);
                if (total >= NS_) break;
            }
        }
        {
            const unsigned m = bq_mask(B, qx, qy, qz);
            if (n0 + 768 < N_) bq_load(base4, ((n0 + 768) >> 2) * 3 + tfo, B);
            if (__ballot_sync(0xffffffffu, m != 0u)) {
                total += bq_place(m, n0 + 256, lane, total, sidx[w]);
                if (total >= NS_) break;
            }
        }
    }

    __syncwarp();
    int v;
    if (total == 0) {
        v = N_ - 1;  // reference: all-invalid -> clamped gather
    } else {
        const int first = sidx[w][0];
        v = (lane < min(total, NS_)) ? sidx[w][lane] : first;
    }
    g_idx[(size_t)q * NS_ + lane] = v;
}

// ---------------------------------------------------------------------------
// Kernel 2: direct grouping, no transpose. One 512-thread block per (b,chan):
// stage the channel row in smem (coalesced float4), then gather with 4-deep
// batched int4 idx loads (explicit MLP=4) + STG.128. 48 warps/SM at 3 blocks.
// ---------------------------------------------------------------------------
__global__ void __launch_bounds__(512) group_direct_kernel(
    const float* __restrict__ xyz, const float* __restrict__ new_xyz,
    const float* __restrict__ feats, float* __restrict__ out) {
    extern __shared__ float row[];           // [N_] (+ [M_] for xyz path)
    const int blk = blockIdx.x;
    const int t   = threadIdx.x;

    if (blk < FEAT_BLOCKS) {
        const int b = blk >> 6;
        const int c = blk & 63;

        const float4* src = (const float4*)(feats + ((size_t)b * C_ + c) * N_);
        float4* row4 = (float4*)row;
#pragma unroll
        for (int i = 0; i < 8; i++)
            row4[t + i * 512] = src[t + i * 512];
        __syncthreads();

        const int4* ib4 = (const int4*)(g_idx + (size_t)b * M_ * NS_);
        float4* ob4 = (float4*)(out + ((size_t)b * COUT_ + 3 + c) * (M_ * NS_));
        // 8192 int4s / 512 threads = 16 per thread, in 4 batches of 4.
#pragma unroll
        for (int e0 = 0; e0 < 4; e0++) {
            int4 id[4];
#pragma unroll
            for (int j = 0; j < 4; j++)
                id[j] = ib4[t + (e0 * 4 + j) * 512];
#pragma unroll
            for (int j = 0; j < 4; j++) {
                float4 v;
                v.x = row[id[j].x]; v.y = row[id[j].y];
                v.z = row[id[j].z]; v.w = row[id[j].w];
                ob4[t + (e0 * 4 + j) * 512] = v;
            }
        }
    } else {
        const int blk2 = blk - FEAT_BLOCKS;
        const int b = blk2 / 3;
        const int c = blk2 % 3;
        float* nq = row + N_;

        for (int i = t; i < N_; i += 512)
            row[i] = xyz[(size_t)b * N_ * 3 + (size_t)i * 3 + c];
        for (int i = t; i < M_; i += 512)
            nq[i] = new_xyz[(size_t)b * M_ * 3 + (size_t)i * 3 + c];
        __syncthreads();

        const int4* ib4 = (const int4*)(g_idx + (size_t)b * M_ * NS_);
        float4* ob4 = (float4*)(out + ((size_t)b * COUT_ + c) * (M_ * NS_));
#pragma unroll
        for (int e0 = 0; e0 < 4; e0++) {
            int4 id[4];
#pragma unroll
            for (int j = 0; j < 4; j++)
                id[j] = ib4[t + (e0 * 4 + j) * 512];
#pragma unroll
            for (int j = 0; j < 4; j++) {
                const int i4 = t + (e0 * 4 + j) * 512;
                const float qv = nq[i4 >> 3];
                float4 v;
                v.x = row[id[j].x] - qv; v.y = row[id[j].y] - qv;
                v.z = row[id[j].z] - qv; v.w = row[id[j].w] - qv;
                ob4[i4] = v;
            }
        }
    }
}

// ---------------------------------------------------------------------------
extern "C" void kernel_launch(void* const* d_in, const int* in_sizes, int n_in,
                              void* d_out, int out_size) {
    const float* xyz = nullptr;
    const float* new_xyz = nullptr;
    const float* feats = nullptr;
    for (int i = 0; i < n_in; i++) {
        if (in_sizes[i] == B_ * N_ * 3)      xyz     = (const float*)d_in[i];
        else if (in_sizes[i] == B_ * M_ * 3) new_xyz = (const float*)d_in[i];
        else if (in_sizes[i] == B_ * C_ * N_) feats  = (const float*)d_in[i];
    }
    float* out = (float*)d_out;

    cudaFuncSetAttribute(group_direct_kernel,
                         cudaFuncAttributeMaxDynamicSharedMemorySize, GD_SMEM);

    ballquery_kernel<<<(B_ * M_) / 4, 128>>>(xyz, new_xyz);
    group_direct_kernel<<<FEAT_BLOCKS + XYZ_BLOCKS, 512, GD_SMEM>>>(
        xyz, new_xyz, feats, out);
}